// round 14
// baseline (speedup 1.0000x reference)
#include <cuda_runtime.h>
#include <cuda_bf16.h>
#include <math.h>
#include <stdint.h>

#define B_ 128
#define T_ 256
#define D_ 256
#define U_ 1024
#define J_ 2048

#define NT_ 64            /* N tiles of 32 pre-cols (= 16 u each) */
#define NCH_ 20           /* K chunks of 64 (16 h + 4 x) */
#define AT_ELEMS 8192     /* A tile 128x64 bf16 */
#define WT_ELEMS 2048     /* W tile 32x64 bf16 */

// ---------------- static device buffers (pre-swizzled bf16 hi/lo tiles) ----------------
__device__ float g_tau[U_];
__device__ __align__(128) __nv_bfloat16 g_Wc_hi[NT_ * NCH_ * WT_ELEMS];  // 5.2MB
__device__ __align__(128) __nv_bfloat16 g_Wc_lo[NT_ * NCH_ * WT_ELEMS];
__device__ __align__(128) __nv_bfloat16 g_X_hi[T_ * 4 * AT_ELEMS];       // 16.8MB
__device__ __align__(128) __nv_bfloat16 g_X_lo[T_ * 4 * AT_ELEMS];
__device__ __align__(128) __nv_bfloat16 g_Ah_hi[2 * 16 * AT_ELEMS];      // 512KB
__device__ __align__(128) __nv_bfloat16 g_Ah_lo[2 * 16 * AT_ELEMS];
__device__ unsigned g_cnt[2 * T_];   // per-step half-grid barrier counters

__device__ __forceinline__ uint32_t swz(uint32_t o) { return o ^ ((o >> 3) & 0x70); }

__device__ __forceinline__ uint32_t smem_u32(const void* p) {
    uint32_t a;
    asm("{ .reg .u64 t; cvta.to.shared.u64 t, %1; cvt.u32.u64 %0, t; }" : "=r"(a) : "l"(p));
    return a;
}

#define CP16(dst, src) \
    asm volatile("cp.async.cg.shared.global [%0], [%1], 16;" :: "r"(dst), "l"(src) : "memory")
#define CP_COMMIT() asm volatile("cp.async.commit_group;" ::: "memory")

#define LDSM4(r0, r1, r2, r3, addr) \
    asm volatile("ldmatrix.sync.aligned.m8n8.x4.shared.b16 {%0,%1,%2,%3}, [%4];" \
        : "=r"(r0), "=r"(r1), "=r"(r2), "=r"(r3) : "r"(addr))

#define MMA(C, a0, a1, a2, a3, b0, b1) \
    asm volatile("mma.sync.aligned.m16n8k16.row.col.f32.bf16.bf16.f32 " \
        "{%0,%1,%2,%3},{%4,%5,%6,%7},{%8,%9},{%0,%1,%2,%3};" \
        : "+f"((C)[0]), "+f"((C)[1]), "+f"((C)[2]), "+f"((C)[3]) \
        : "r"(a0), "r"(a1), "r"(a2), "r"(a3), "r"(b0), "r"(b1))

// ---------------- single fused prep kernel ----------------
// blocks [0,1280): W tiles ; [1280,2304): X tiles ; [2304,2320): h0 tiles ; 2320: tau+reset
__global__ void __launch_bounds__(256) prep_all(
    const float* __restrict__ Wh, const float* __restrict__ Wx,
    const float* __restrict__ feats, const float* __restrict__ h0,
    const float* __restrict__ w_tau)
{
    const int bid = blockIdx.x;
    if (bid < 1280) {
        int nTile = bid / NCH_, ch = bid % NCH_;
        char* dh = (char*)(g_Wc_hi + (nTile * NCH_ + ch) * WT_ELEMS);
        char* dl = (char*)(g_Wc_lo + (nTile * NCH_ + ch) * WT_ELEMS);
        for (int i = threadIdx.x; i < WT_ELEMS; i += 256) {
            int r = i >> 6, kc = i & 63;
            int n = nTile * 32 + r;
            int u = n >> 1;
            int col = (n & 1) ? (U_ + u) : u;
            int k = ch * 64 + kc;
            float v = (k < U_) ? Wh[(size_t)k * J_ + col] : Wx[(size_t)(k - U_) * J_ + col];
            __nv_bfloat16 hi = __float2bfloat16(v);
            __nv_bfloat16 lo = __float2bfloat16(v - __bfloat162float(hi));
            uint32_t off = swz((uint32_t)(r * 128 + kc * 2));
            *(__nv_bfloat16*)(dh + off) = hi;
            *(__nv_bfloat16*)(dl + off) = lo;
        }
    } else if (bid < 2304) {
        int q = bid - 1280;
        int t = q >> 2, cx = q & 3;
        char* dh = (char*)(g_X_hi + (t * 4 + cx) * AT_ELEMS);
        char* dl = (char*)(g_X_lo + (t * 4 + cx) * AT_ELEMS);
        for (int i = threadIdx.x; i < AT_ELEMS; i += 256) {
            int m = i >> 6, kc = i & 63;
            float v = feats[((size_t)m * T_ + t) * D_ + cx * 64 + kc];
            __nv_bfloat16 hi = __float2bfloat16(v);
            __nv_bfloat16 lo = __float2bfloat16(v - __bfloat162float(hi));
            uint32_t off = swz((uint32_t)(m * 128 + kc * 2));
            *(__nv_bfloat16*)(dh + off) = hi;
            *(__nv_bfloat16*)(dl + off) = lo;
        }
    } else if (bid < 2320) {
        int ch = bid - 2304;
        char* dh = (char*)(g_Ah_hi + ch * AT_ELEMS);
        char* dl = (char*)(g_Ah_lo + ch * AT_ELEMS);
        for (int i = threadIdx.x; i < AT_ELEMS; i += 256) {
            int m = i >> 6, kc = i & 63;
            float v = h0[(size_t)m * U_ + ch * 64 + kc];
            __nv_bfloat16 hi = __float2bfloat16(v);
            __nv_bfloat16 lo = __float2bfloat16(v - __bfloat162float(hi));
            uint32_t off = swz((uint32_t)(m * 128 + kc * 2));
            *(__nv_bfloat16*)(dh + off) = hi;
            *(__nv_bfloat16*)(dl + off) = lo;
        }
    } else {
        for (int u = threadIdx.x; u < U_; u += 256) {
            float w = w_tau[u];
            g_tau[u] = (w > 20.f) ? w : log1pf(expf(w));
        }
        for (int i = threadIdx.x; i < 2 * T_; i += 256) g_cnt[i] = 0;
    }
}

// ---------------- persistent kernel ----------------
// per-step chunk order: pos 0..3 -> x chunks, pos 4..19 -> h chunks 0..15
// smem: A stages 4 x 16KB @0 ; W resident 20 x 8KB @65536 (indexed by pos)
#define A_STAGE_B 16384
#define W_BASE    65536
#define SMEM_TOTAL (1024 + 4 * A_STAGE_B + NCH_ * 8192)
#define TOTAL_CH (T_ * NCH_)

__global__ void __launch_bounds__(256, 1) rnn_kernel(
    const float* __restrict__ h0,
    const float* __restrict__ bias,
    const float* __restrict__ tsteps,
    float* __restrict__ out)
{
    extern __shared__ char smem[];
    const uint32_t sA = (smem_u32(smem) + 1023u) & ~1023u;
    const uint32_t sW = sA + W_BASE;

    const int tid = threadIdx.x;
    const int wid = tid >> 5, lid = tid & 31;
    const int wm = wid & 3, wn = wid >> 2;        // warp tile 16 rows x 16 cols
    const int bid = blockIdx.x;
    const int mh = bid >> 6;
    const int nt = bid & 63;

    // ---- load resident W tiles, ordered by pipeline position ----
    {
        const uint32_t o = (uint32_t)tid * 16u;
#pragma unroll
        for (int pos = 0; pos < NCH_; pos++) {
            const int c = (pos < 4) ? (16 + pos) : (pos - 4);
            const uint32_t wst = sW + (uint32_t)pos * 8192u;
            CP16(wst + o, (const char*)(g_Wc_hi + (nt * NCH_ + c) * WT_ELEMS) + o);
            CP16(wst + 4096 + o, (const char*)(g_Wc_lo + (nt * NCH_ + c) * WT_ELEMS) + o);
        }
        CP_COMMIT();
        asm volatile("cp.async.wait_group 0;" ::: "memory");
        __syncthreads();
    }

    // ---- per-thread constants & persistent h state ----
    const int g = lid >> 2, q = lid & 3;
    const int mBase = mh * 64 + wm * 16 + g;
    int ua[2]; float bf[2], ba[2], tauv[2];
#pragma unroll
    for (int blk = 0; blk < 2; blk++) {
        ua[blk]   = nt * 16 + wn * 8 + blk * 4 + q;
        bf[blk]   = bias[ua[blk]];
        ba[blk]   = bias[U_ + ua[blk]];
        tauv[blk] = g_tau[ua[blk]];
    }
    float hp[4];
#pragma unroll
    for (int blk = 0; blk < 2; blk++)
#pragma unroll
        for (int rr = 0; rr < 2; rr++)
            hp[blk * 2 + rr] = h0[(size_t)(mBase + rr * 8) * U_ + ua[blk]];

    // ldmatrix address components
    const int rowA = wm * 16 + (lid & 15);
    const uint32_t rowAoff = (uint32_t)rowA * 128u;
    const uint32_t xrA = (uint32_t)(rowA & 7) << 4;
    const int rowW = wn * 16 + (lid & 15);
    const uint32_t rowWoff = (uint32_t)rowW * 128u;
    const uint32_t xrW = (uint32_t)(rowW & 7) << 4;
    const uint32_t kbsel = (uint32_t)(lid >> 4) << 4;
    const uint32_t aOff = (uint32_t)tid * 16u;

    // 6 independent accumulator chains (term x n-slot)
    float Chh0[4] = {0,0,0,0}, Chh1[4] = {0,0,0,0};
    float Chl0[4] = {0,0,0,0}, Chl1[4] = {0,0,0,0};
    float Clh0[4] = {0,0,0,0}, Clh1[4] = {0,0,0,0};

    // ---- issue-stream state (3 chunks ahead; 4 stages) ----
    int iPos = 0, iT = 0, iStg = 0;
    auto issueA = [&]() {
        const uint32_t stg = sA + (uint32_t)iStg * A_STAGE_B;
        const char *sh, *sl;
        if (iPos < 4) {
            sh = (const char*)(g_X_hi + (iT * 4 + iPos) * AT_ELEMS) + mh * 8192;
            sl = (const char*)(g_X_lo + (iT * 4 + iPos) * AT_ELEMS) + mh * 8192;
        } else {
            const int c = iPos - 4;
            const int par = iT & 1;
            sh = (const char*)(g_Ah_hi + (par * 16 + c) * AT_ELEMS) + mh * 8192;
            sl = (const char*)(g_Ah_lo + (par * 16 + c) * AT_ELEMS) + mh * 8192;
        }
        CP16(stg + aOff, sh + aOff);
        CP16(stg + 4096 + aOff, sh + 4096 + aOff);
        CP16(stg + 8192 + aOff, sl + aOff);
        CP16(stg + 12288 + aOff, sl + 4096 + aOff);
        CP_COMMIT();
        if (++iStg == 4) iStg = 0;
        if (++iPos == NCH_) { iPos = 0; iT++; }
    };

    issueA(); issueA(); issueA();

    // fragment double buffers
    uint32_t fa[2][4], fe[2][4], fw[2][4], fx[2][4];

#define LD_FRAG(bb, k16) do { \
        const uint32_t kb = (uint32_t)(k16) * 32u + kbsel; \
        const uint32_t aA = stgA + rowAoff + (kb ^ xrA); \
        const uint32_t aW = wst + rowWoff + (kb ^ xrW); \
        LDSM4(fa[bb][0], fa[bb][1], fa[bb][2], fa[bb][3], aA); \
        LDSM4(fe[bb][0], fe[bb][1], fe[bb][2], fe[bb][3], aA + 8192); \
        LDSM4(fw[bb][0], fw[bb][1], fw[bb][2], fw[bb][3], aW); \
        LDSM4(fx[bb][0], fx[bb][1], fx[bb][2], fx[bb][3], aW + 4096); \
    } while (0)

#define DO_MMA(bb) do { \
        MMA(Chh0, fa[bb][0], fa[bb][1], fa[bb][2], fa[bb][3], fw[bb][0], fw[bb][2]); \
        MMA(Chl0, fa[bb][0], fa[bb][1], fa[bb][2], fa[bb][3], fx[bb][0], fx[bb][2]); \
        MMA(Clh0, fe[bb][0], fe[bb][1], fe[bb][2], fe[bb][3], fw[bb][0], fw[bb][2]); \
        MMA(Chh1, fa[bb][0], fa[bb][1], fa[bb][2], fa[bb][3], fw[bb][1], fw[bb][3]); \
        MMA(Chl1, fa[bb][0], fa[bb][1], fa[bb][2], fa[bb][3], fx[bb][1], fx[bb][3]); \
        MMA(Clh1, fe[bb][0], fe[bb][1], fe[bb][2], fe[bb][3], fw[bb][1], fw[bb][3]); \
    } while (0)

    int pos = 0, t = 0, stg = 0;
#pragma unroll 1
    for (int gi = 0; gi < TOTAL_CH; gi++) {
        if (gi <= TOTAL_CH - 3) {
            asm volatile("cp.async.wait_group 2;" ::: "memory");
        } else if (gi == TOTAL_CH - 2) {
            asm volatile("cp.async.wait_group 1;" ::: "memory");
        } else {
            asm volatile("cp.async.wait_group 0;" ::: "memory");
        }

        // before issuing the first h-chunk of step iT, ensure step iT-1 published
        if (iPos == 4 && iT > 0 && gi + 3 < TOTAL_CH && tid == 0) {
            const unsigned* cp = &g_cnt[(unsigned)(iT - 1) * 2u + (unsigned)mh];
            unsigned v;
            do {
                asm volatile("ld.acquire.gpu.global.u32 %0, [%1];" : "=r"(v) : "l"(cp) : "memory");
            } while (v < 64u);
        }
        __syncthreads();
        if (gi + 3 < TOTAL_CH) issueA();

        const uint32_t stgA = sA + (uint32_t)stg * A_STAGE_B;
        const uint32_t wst = sW + (uint32_t)pos * 8192u;

        // software-pipelined LDSM->MMA over 4 k16 slices
        LD_FRAG(0, 0);
        LD_FRAG(1, 1);
        DO_MMA(0);
        LD_FRAG(0, 2);
        DO_MMA(1);
        LD_FRAG(1, 3);
        DO_MMA(0);
        DO_MMA(1);

        if (pos == NCH_ - 1) {
            // ---- LTC epilogue (registers only, fast-math) ----
            const int p1 = (t & 1) ^ 1;
            const float dt0 = tsteps[(size_t)mBase * T_ + t];
            const float dt1 = tsteps[(size_t)(mBase + 8) * T_ + t];
            float* Ch[2] = {Chh0, Chh1};
            float* Cl1a[2] = {Chl0, Chl1};
            float* Cl2a[2] = {Clh0, Clh1};
#pragma unroll
            for (int blk = 0; blk < 2; blk++) {
                const int u = ua[blk];
                char* th = (char*)(g_Ah_hi + (p1 * 16 + (u >> 6)) * AT_ELEMS);
                char* tl = (char*)(g_Ah_lo + (p1 * 16 + (u >> 6)) * AT_ELEMS);
#pragma unroll
                for (int rr = 0; rr < 2; rr++) {
                    const int m = mBase + rr * 8;
                    float pre_f = (Ch[blk][rr*2+0] + Cl1a[blk][rr*2+0]) + Cl2a[blk][rr*2+0] + bf[blk];
                    float pre_a = (Ch[blk][rr*2+1] + Cl1a[blk][rr*2+1]) + Cl2a[blk][rr*2+1] + ba[blk];
                    float f = fdividef(1.f, 1.f + __expf(-pre_f));
                    float ta = __expf(-2.f * fabsf(pre_a));
                    float a = copysignf(fdividef(1.f - ta, 1.f + ta), pre_a);
                    float dtv = rr ? dt1 : dt0;
                    float hn = (hp[blk * 2 + rr] - a) * __expf(-dtv * (tauv[blk] + f)) + a;
                    hp[blk * 2 + rr] = hn;
                    out[((size_t)m * T_ + t) * U_ + u] = hn;
                    __nv_bfloat16 hi = __float2bfloat16(hn);
                    __nv_bfloat16 lo = __float2bfloat16(hn - __bfloat162float(hi));
                    uint32_t off = swz((uint32_t)(m * 128 + (u & 63) * 2));
                    *(__nv_bfloat16*)(th + off) = hi;
                    *(__nv_bfloat16*)(tl + off) = lo;
                    Ch[blk][rr*2+0] = 0.f;  Ch[blk][rr*2+1] = 0.f;
                    Cl1a[blk][rr*2+0] = 0.f; Cl1a[blk][rr*2+1] = 0.f;
                    Cl2a[blk][rr*2+0] = 0.f; Cl2a[blk][rr*2+1] = 0.f;
                }
            }
            // ---- publish step t (arrive only; wait at pos1 of step t+1) ----
            if (t + 1 < T_) {
                __syncthreads();
                if (tid == 0) {
                    unsigned* cp = &g_cnt[(unsigned)t * 2u + (unsigned)mh];
                    asm volatile("fence.acq_rel.gpu;" ::: "memory");
                    asm volatile("red.release.gpu.global.add.u32 [%0], %1;" :: "l"(cp), "r"(1u) : "memory");
                }
            }
        }

        if (++stg == 4) stg = 0;
        if (++pos == NCH_) { pos = 0; t++; }
    }
#undef LD_FRAG
#undef DO_MMA
}

// ---------------- launch ----------------
extern "C" void kernel_launch(void* const* d_in, const int* in_sizes, int n_in,
                              void* d_out, int out_size) {
    (void)in_sizes; (void)n_in; (void)out_size;
    const float* feats  = (const float*)d_in[0];
    const float* tsteps = (const float*)d_in[1];
    const float* Wx     = (const float*)d_in[2];
    const float* Wh     = (const float*)d_in[3];
    const float* bias   = (const float*)d_in[4];
    const float* w_tau  = (const float*)d_in[5];
    const float* h0     = (const float*)d_in[6];
    float* out = (float*)d_out;

    static int smem_set = 0;
    if (!smem_set) {
        cudaFuncSetAttribute(rnn_kernel, cudaFuncAttributeMaxDynamicSharedMemorySize, SMEM_TOTAL);
        smem_set = 1;
    }

    prep_all<<<2321, 256>>>(Wh, Wx, feats, h0, w_tau);
    rnn_kernel<<<128, 256, SMEM_TOTAL>>>(h0, bias, tsteps, out);
}